// round 16
// baseline (speedup 1.0000x reference)
#include <cuda_runtime.h>
#include <math.h>
#include <stdint.h>

#define B 64
#define CHI 20
#define D 65536                 // floats per frame
#define D4 (D / 4)
#define BPB 128                 // blocks per batch
#define SLICE4 2560             // float4 per slice = 40 KB (= CHI*D4/BPB)
#define ROWS 10                 // 1024-float rows per slice
#define DPB 512                 // d-outputs per block
#define CONC 2                  // concurrent batch groups
#define NITER (B / CONC)        // 32
#define NBLK (CONC * BPB)       // 256 blocks; 2/SM -> all co-resident
#define THREADS 256
#define SMEM_DYN (2 * SLICE4 * 16)   // 81920 B, double buffer

__device__ float g_part[B * BPB * 2];      // per-block partials (c0, c0+1)
__device__ unsigned g_bar[CONC * NITER];

__global__ void init_kernel() {
    if (threadIdx.x < CONC * NITER) g_bar[threadIdx.x] = 0u;
}

__device__ __forceinline__ uint32_t smem_u32(const void* p) {
    return (uint32_t)__cvta_generic_to_shared(p);
}
__device__ __forceinline__ void cp16(uint32_t dst, const float4* src) {
    asm volatile("cp.async.cg.shared.global [%0], [%1], 16;\n" :: "r"(dst), "l"(src));
}

// ---------------------------------------------------------------------------
// Fused kernel with async double-buffered staging.
// Block (g, j) iterates batches b = it*CONC + g:
//   - wait cp.async slice (issued one iteration ago)  [40 KB contiguous]
//   - issue cp.async for next batch's slice           [DRAM busy hereafter]
//   - phase 1: slice rows paired with frame19 window (true frames-major dots)
//   - group barrier + block-parallel gather + softmax
//   - phase 2: d-major weighted sum from the SAME staged bytes
// Each input byte crosses DRAM exactly once.
// ---------------------------------------------------------------------------
__global__ __launch_bounds__(THREADS, 2)
void fused_kernel(const float* __restrict__ x, float* __restrict__ out) {
    extern __shared__ float4 sbuf[];         // 2 * SLICE4
    __shared__ float sred[2][8];
    __shared__ float s_scores[CHI];
    __shared__ float s_alpha[CHI];

    const int g    = blockIdx.x / BPB;
    const int j    = blockIdx.x % BPB;
    const int tid  = threadIdx.x;
    const int warp = tid >> 5;
    const int lane = tid & 31;
    const uint32_t sbase = smem_u32(sbuf);
    const float4* __restrict__ x4 = reinterpret_cast<const float4*>(x);

    // prologue: prefetch slice of batch g into buffer 0
    {
        const float4* src = x4 + (size_t)g * (CHI * D4) + (size_t)j * SLICE4;
        #pragma unroll
        for (int u = 0; u < ROWS; u++) {
            const int idx = u * THREADS + tid;
            cp16(sbase + idx * 16, src + idx);
        }
        asm volatile("cp.async.commit_group;\n" ::: "memory");
    }

    for (int it = 0; it < NITER; it++) {
        const int b   = it * CONC + g;
        const int cur = it & 1;
        const float4* s4 = sbuf + cur * SLICE4;

        asm volatile("cp.async.wait_group 0;\n" ::: "memory");
        __syncthreads();   // slice ready; also orders prev phase-2 reads
                           // before the cp.async below reuses the other buffer

        if (it + 1 < NITER) {
            const float4* src =
                x4 + (size_t)(b + CONC) * (CHI * D4) + (size_t)j * SLICE4;
            const uint32_t dst = sbase + (uint32_t)(cur ^ 1) * (SLICE4 * 16);
            #pragma unroll
            for (int u = 0; u < ROWS; u++) {
                const int idx = u * THREADS + tid;
                cp16(dst + idx * 16, src + idx);
            }
            asm volatile("cp.async.commit_group;\n" ::: "memory");
        }

        // ---------- phase 1: frames-major dots from staged slice -------------
        // slice row m = 10j+r holds frames[m/64][ (m%64)*1024 .. +1024 );
        // partner = frame19 same e-range (L2-hot 256 KB region).
        const float4* __restrict__ f19 =
            x4 + (size_t)b * (CHI * D4) + (size_t)(CHI - 1) * D4;
        const int c0 = (10 * j) >> 6;
        float a0 = 0.f, a1 = 0.f;
        #pragma unroll
        for (int r = 0; r < ROWS; r++) {
            const int m = 10 * j + r;
            const float4 p = __ldg(f19 + ((m & 63) << 8) + tid);
            const float4 s = s4[r * THREADS + tid];
            const float dt = fmaf(s.x, p.x, fmaf(s.y, p.y,
                             fmaf(s.z, p.z, s.w * p.w)));
            if ((m >> 6) == c0) a0 += dt; else a1 += dt;
        }
        #pragma unroll
        for (int o = 16; o; o >>= 1) {
            a0 += __shfl_xor_sync(0xFFFFFFFFu, a0, o);
            a1 += __shfl_xor_sync(0xFFFFFFFFu, a1, o);
        }
        if (lane == 0) { sred[0][warp] = a0; sred[1][warp] = a1; }
        __syncthreads();
        if (tid < 2) {
            float v = 0.f;
            #pragma unroll
            for (int w = 0; w < 8; w++) v += sred[tid][w];
            g_part[((size_t)b * BPB + j) * 2 + tid] = v;
        }
        __threadfence();               // release partials
        __syncthreads();

        // ---------- group barrier (all 256 blocks co-resident) ---------------
        if (tid == 0) {
            unsigned* ctr = &g_bar[g * NITER + it];
            atomicAdd(ctr, 1u);
            while (*(volatile unsigned*)ctr < (unsigned)BPB) __nanosleep(64);
            __threadfence();           // acquire
        }
        if (tid < CHI) s_scores[tid] = 0.f;
        __syncthreads();

        // ---------- gather partials -> s_scores (block-parallel) -------------
        {
            const int jj = tid >> 1, slot = tid & 1;
            const float v = g_part[((size_t)b * BPB + jj) * 2 + slot];
            const int c = ((10 * jj) >> 6) + slot;
            if (c < CHI) atomicAdd(&s_scores[c], v);
        }
        __syncthreads();

        // ---------- softmax (warp 0) ------------------------------------------
        if (warp == 0) {
            const float s = (lane < CHI) ? s_scores[lane] * (1.0f / CHI)
                                         : -INFINITY;
            float mx = s;
            #pragma unroll
            for (int o = 16; o; o >>= 1)
                mx = fmaxf(mx, __shfl_xor_sync(0xFFFFFFFFu, mx, o));
            const float e = (lane < CHI) ? expf(s - mx) : 0.f;
            float sum = e;
            #pragma unroll
            for (int o = 16; o; o >>= 1)
                sum += __shfl_xor_sync(0xFFFFFFFFu, sum, o);
            if (lane < CHI) s_alpha[lane] = e / sum;
        }
        __syncthreads();

        float a[CHI];
        #pragma unroll
        for (int c = 0; c < CHI; c++) a[c] = s_alpha[c];

        // ---------- phase 2: d-major weighted sum from same staged bytes -----
        #pragma unroll
        for (int k = 0; k < 2; k++) {
            const int ld = k * THREADS + tid;          // local d (0..511)
            const float4* row = s4 + (size_t)ld * 5;   // 20 contiguous floats
            float v = 0.f;
            #pragma unroll
            for (int i = 0; i < 5; i++) {
                const float4 r = row[i];
                v = fmaf(r.x, a[4 * i + 0], fmaf(r.y, a[4 * i + 1],
                    fmaf(r.z, a[4 * i + 2], fmaf(r.w, a[4 * i + 3], v))));
            }
            out[(size_t)b * D + j * DPB + ld] = v;
        }
        // buffer-reuse ordering handled by top-of-loop __syncthreads
    }
}

extern "C" void kernel_launch(void* const* d_in, const int* in_sizes, int n_in,
                              void* d_out, int out_size) {
    const float* x = (const float*)d_in[0];
    float* out = (float*)d_out;

    static bool attr_set = false;
    if (!attr_set) {
        cudaFuncSetAttribute(fused_kernel,
                             cudaFuncAttributeMaxDynamicSharedMemorySize,
                             SMEM_DYN);
        attr_set = true;
    }

    init_kernel<<<1, 64>>>();
    fused_kernel<<<NBLK, THREADS, SMEM_DYN>>>(x, out);
}